// round 8
// baseline (speedup 1.0000x reference)
#include <cuda_runtime.h>
#include <cuda_bf16.h>
#include <cuda_fp16.h>
#include <cstdint>
#include <math.h>
#include <float.h>

#define N_ROWS 32768
#define K_PROTO 1024
#define D_DIM 256

// ---- scratch (device globals: no cudaMalloc allowed) ----
__device__ __half         g_logitsh[(size_t)N_ROWS * K_PROTO]; // 64 MB, u = v + x2[row]
__device__ float2         g_rpart[(size_t)N_ROWS * 32];        // per (row, 32-col slice) {max v, idx}
__device__ float          g_x2[N_ROWS];
__device__ float          g_p2[K_PROTO];
__device__ __nv_bfloat16  g_xhi[(size_t)N_ROWS * D_DIM];
__device__ __nv_bfloat16  g_xlo[(size_t)N_ROWS * D_DIM];
__device__ __nv_bfloat16  g_phi[(size_t)K_PROTO * D_DIM];
__device__ __nv_bfloat16  g_plo[(size_t)K_PROTO * D_DIM];
__device__ float          g_part_y[256 * K_PROTO];             // colsum(y_soft) per softmax block
__device__ float          g_vpart[512 * K_PROTO];              // colsum(v) per (m_block, wm)
__device__ double         g_part_lse[256];                     // sum(lse) per softmax block
__device__ double         g_coly[K_PROTO];
__device__ double         g_colv[K_PROTO];

__device__ __forceinline__ uint32_t smem_u32(const void* p) {
    uint32_t a;
    asm("{ .reg .u64 t; cvta.to.shared.u64 t, %1; cvt.u32.u64 %0, t; }"
        : "=r"(a) : "l"(p));
    return a;
}
__device__ __forceinline__ void cp16(uint32_t saddr, const void* g) {
    asm volatile("cp.async.cg.shared.global [%0], [%1], 16;" :: "r"(saddr), "l"(g) : "memory");
}

// ===========================================================================
// K0: fused prep — warp per row: bf16 hi/lo split + row squared norm.
// ===========================================================================
__global__ void prep_kernel(const float* __restrict__ src,
                            __nv_bfloat16* __restrict__ hi,
                            __nv_bfloat16* __restrict__ lo,
                            float* __restrict__ sq, int rows)
{
    int warp = (blockIdx.x * blockDim.x + threadIdx.x) >> 5;
    int lane = threadIdx.x & 31;
    if (warp >= rows) return;
    const float4* s = (const float4*)(src + (size_t)warp * D_DIM);
    uint2* H = (uint2*)(hi + (size_t)warp * D_DIM);
    uint2* L = (uint2*)(lo + (size_t)warp * D_DIM);
    float acc = 0.f;
#pragma unroll
    for (int i = 0; i < 2; ++i) {
        int c = lane + 32 * i;
        float4 v = __ldg(&s[c]);
        acc += v.x * v.x + v.y * v.y + v.z * v.z + v.w * v.w;
        __nv_bfloat16 h0 = __float2bfloat16(v.x), h1 = __float2bfloat16(v.y);
        __nv_bfloat16 h2 = __float2bfloat16(v.z), h3 = __float2bfloat16(v.w);
        __nv_bfloat16 l0 = __float2bfloat16(v.x - __bfloat162float(h0));
        __nv_bfloat16 l1 = __float2bfloat16(v.y - __bfloat162float(h1));
        __nv_bfloat16 l2 = __float2bfloat16(v.z - __bfloat162float(h2));
        __nv_bfloat16 l3 = __float2bfloat16(v.w - __bfloat162float(h3));
        __nv_bfloat162 a; a.x = h0; a.y = h1;
        __nv_bfloat162 b; b.x = h2; b.y = h3;
        uint2 hv; hv.x = *(uint32_t*)&a; hv.y = *(uint32_t*)&b;
        __nv_bfloat162 cpl; cpl.x = l0; cpl.y = l1;
        __nv_bfloat162 dpl; dpl.x = l2; dpl.y = l3;
        uint2 lv; lv.x = *(uint32_t*)&cpl; lv.y = *(uint32_t*)&dpl;
        H[c] = hv;
        L[c] = lv;
    }
#pragma unroll
    for (int off = 16; off; off >>= 1)
        acc += __shfl_xor_sync(0xffffffffu, acc, off);
    if (lane == 0) sq[warp] = acc;
}

// ===========================================================================
// K1: bf16 mma.sync GEMM (3-term split over K_eff=768 in 12 k64 stages)
//     CTA 128x256, 512 threads, warp tile 64x32, 4-stage cp.async pipeline.
//     epilogue: exact fp32 v = 2dot+g-x2-p2 -> argmax partials + colsum(v),
//     store fp16 of u = v + x2 (row-shifted, O(1-10) scale).
// ===========================================================================
#define MT 128
#define NT 256
#define STAGE_BYTES 49152          // A 16K + B 32K
#define GEMM_SMEM   (4 * STAGE_BYTES)   // 192 KB

__device__ __forceinline__ void issue_stage(int c, uint32_t sbase, int m0, int n0, int tid)
{
    const int term = c >> 2;
    const int koff = (c & 3) * 64;
    const __nv_bfloat16* As = (term == 2) ? g_xlo : g_xhi;
    const __nv_bfloat16* Bs = (term == 1) ? g_plo : g_phi;
    const uint32_t bufA = sbase + (uint32_t)(c & 3) * STAGE_BYTES;
    const uint32_t bufB = bufA + 16384;
#pragma unroll
    for (int it = 0; it < 2; ++it) {
        int i = tid + 512 * it, row = i >> 3, cc = i & 7;
        cp16(bufA + row * 128 + ((cc ^ (row & 7)) << 4),
             As + (size_t)(m0 + row) * D_DIM + koff + cc * 8);
    }
#pragma unroll
    for (int it = 0; it < 4; ++it) {
        int i = tid + 512 * it, row = i >> 3, cc = i & 7;
        cp16(bufB + row * 128 + ((cc ^ (row & 7)) << 4),
             Bs + (size_t)(n0 + row) * D_DIM + koff + cc * 8);
    }
    asm volatile("cp.async.commit_group;" ::: "memory");
}

__global__ void __launch_bounds__(512, 1)
gemm_mma_kernel(const float* __restrict__ G)
{
    extern __shared__ __align__(128) char sm[];
    const uint32_t sbase = smem_u32(sm);
    const int tid  = threadIdx.x;
    const int warp = tid >> 5;
    const int lane = tid & 31;
    const int wm   = warp >> 3;          // 0..1
    const int wn   = warp & 7;           // 0..7
    const int m0   = blockIdx.y * MT;
    const int n0   = blockIdx.x * NT;

    float d[4][4][4];
#pragma unroll
    for (int mi = 0; mi < 4; ++mi)
#pragma unroll
        for (int ni = 0; ni < 4; ++ni)
#pragma unroll
            for (int q = 0; q < 4; ++q) d[mi][ni][q] = 0.f;

    issue_stage(0, sbase, m0, n0, tid);
    issue_stage(1, sbase, m0, n0, tid);
    issue_stage(2, sbase, m0, n0, tid);

    for (int c = 0; c < 12; ++c) {
        if (c < 10)       asm volatile("cp.async.wait_group 2;" ::: "memory");
        else if (c == 10) asm volatile("cp.async.wait_group 1;" ::: "memory");
        else              asm volatile("cp.async.wait_group 0;" ::: "memory");
        __syncthreads();
        if (c + 3 < 12) issue_stage(c + 3, sbase, m0, n0, tid);

        const uint32_t bufA = sbase + (uint32_t)(c & 3) * STAGE_BYTES;
        const uint32_t bufB = bufA + 16384;
#pragma unroll
        for (int ks = 0; ks < 4; ++ks) {
            uint32_t a[16], br[8];
#pragma unroll
            for (int mi = 0; mi < 4; ++mi) {
                int row = wm * 64 + mi * 16 + (lane & 15);
                int cc  = ks * 2 + (lane >> 4);
                uint32_t ad = bufA + row * 128 + ((cc ^ (row & 7)) << 4);
                asm volatile("ldmatrix.sync.aligned.m8n8.x4.shared.b16 {%0,%1,%2,%3}, [%4];"
                    : "=r"(a[mi*4+0]), "=r"(a[mi*4+1]), "=r"(a[mi*4+2]), "=r"(a[mi*4+3])
                    : "r"(ad));
            }
#pragma unroll
            for (int p = 0; p < 2; ++p) {
                int nrow = wn * 32 + p * 16 + ((lane >> 4) << 3) + (lane & 7);
                int cc   = ks * 2 + ((lane >> 3) & 1);
                uint32_t bd = bufB + nrow * 128 + ((cc ^ (nrow & 7)) << 4);
                asm volatile("ldmatrix.sync.aligned.m8n8.x4.shared.b16 {%0,%1,%2,%3}, [%4];"
                    : "=r"(br[p*4+0]), "=r"(br[p*4+1]), "=r"(br[p*4+2]), "=r"(br[p*4+3])
                    : "r"(bd));
            }
#pragma unroll
            for (int mi = 0; mi < 4; ++mi)
#pragma unroll
                for (int ni = 0; ni < 4; ++ni) {
                    asm volatile(
                        "mma.sync.aligned.m16n8k16.row.col.f32.bf16.bf16.f32 "
                        "{%0,%1,%2,%3}, {%4,%5,%6,%7}, {%8,%9}, {%0,%1,%2,%3};"
                        : "+f"(d[mi][ni][0]), "+f"(d[mi][ni][1]),
                          "+f"(d[mi][ni][2]), "+f"(d[mi][ni][3])
                        : "r"(a[mi*4+0]), "r"(a[mi*4+1]), "r"(a[mi*4+2]), "r"(a[mi*4+3]),
                          "r"(br[ni*2+0]), "r"(br[ni*2+1]));
                }
        }
    }

    // ---- epilogue: exact v for argmax/colsum; fp16 store of u = v + x2 ----
    float cs[8];
#pragma unroll
    for (int j = 0; j < 8; ++j) cs[j] = 0.f;
    float rmax[8];
    int   rarg[8];
#pragma unroll
    for (int q = 0; q < 8; ++q) { rmax[q] = -FLT_MAX; rarg[q] = 0; }

#pragma unroll
    for (int mi = 0; mi < 4; ++mi) {
        int r0 = m0 + wm * 64 + mi * 16 + (lane >> 2);
        float x20 = g_x2[r0], x21 = g_x2[r0 + 8];
#pragma unroll
        for (int ni = 0; ni < 4; ++ni) {
            int col = n0 + wn * 32 + ni * 8 + (lane & 3) * 2;
            float2 p2v = *(const float2*)&g_p2[col];
            float2 ga = __ldg((const float2*)(G + (size_t)r0 * K_PROTO + col));
            float2 gb = __ldg((const float2*)(G + (size_t)(r0 + 8) * K_PROTO + col));
            float2 o0, o1;
            o0.x = fmaf(2.f, d[mi][ni][0], ga.x) - x20 - p2v.x;
            o0.y = fmaf(2.f, d[mi][ni][1], ga.y) - x20 - p2v.y;
            o1.x = fmaf(2.f, d[mi][ni][2], gb.x) - x21 - p2v.x;
            o1.y = fmaf(2.f, d[mi][ni][3], gb.y) - x21 - p2v.y;
            // row-shifted u = v + x2 (O(1-10) scale) -> fp16
            __half2 h0 = __floats2half2_rn(o0.x + x20, o0.y + x20);
            __half2 h1 = __floats2half2_rn(o1.x + x21, o1.y + x21);
            *(uint32_t*)(g_logitsh + (size_t)r0 * K_PROTO + col)       = *(uint32_t*)&h0;
            *(uint32_t*)(g_logitsh + (size_t)(r0 + 8) * K_PROTO + col) = *(uint32_t*)&h1;
            cs[ni * 2 + 0] += o0.x + o1.x;
            cs[ni * 2 + 1] += o0.y + o1.y;
            int s0 = mi * 2, s1 = mi * 2 + 1;
            if (o0.x > rmax[s0]) { rmax[s0] = o0.x; rarg[s0] = col; }
            if (o0.y > rmax[s0]) { rmax[s0] = o0.y; rarg[s0] = col + 1; }
            if (o1.x > rmax[s1]) { rmax[s1] = o1.x; rarg[s1] = col; }
            if (o1.y > rmax[s1]) { rmax[s1] = o1.y; rarg[s1] = col + 1; }
        }
    }
    // reduce max/arg over the 4 lanes sharing each row (xor 1,2)
#pragma unroll
    for (int q = 0; q < 8; ++q) {
#pragma unroll
        for (int off = 1; off <= 2; off <<= 1) {
            float om = __shfl_xor_sync(0xffffffffu, rmax[q], off);
            int   oi = __shfl_xor_sync(0xffffffffu, rarg[q], off);
            if (om > rmax[q] || (om == rmax[q] && oi < rarg[q])) { rmax[q] = om; rarg[q] = oi; }
        }
    }
    // one slot per (row, warp n-slice): slot = blockIdx.x*8 + wn (ascending col order)
    if ((lane & 3) == 0) {
        const int slot = blockIdx.x * 8 + wn;
#pragma unroll
        for (int q = 0; q < 8; ++q) {
            int row = m0 + wm * 64 + (q >> 1) * 16 + (q & 1) * 8 + (lane >> 2);
            g_rpart[(size_t)row * 32 + slot] =
                make_float2(rmax[q], __int_as_float(rarg[q]));
        }
    }
    // colsum(v): reduce over the 8 lanes sharing each column (xor 4,8,16)
#pragma unroll
    for (int j = 0; j < 8; ++j) {
#pragma unroll
        for (int off = 4; off <= 16; off <<= 1)
            cs[j] += __shfl_xor_sync(0xffffffffu, cs[j], off);
    }
    if (lane < 4) {
        float* dst = g_vpart + (size_t)(blockIdx.y * 2 + wm) * K_PROTO;
#pragma unroll
        for (int j = 0; j < 8; ++j) {
            int col = n0 + wn * 32 + (j >> 1) * 8 + lane * 2 + (j & 1);
            dst[col] = cs[j];
        }
    }
}

// ===========================================================================
// K2: softmax stats from fp16 shifted logits + precomputed argmax; gather.
// ===========================================================================
__global__ void __launch_bounds__(256)
softmax_kernel(const float* __restrict__ P, float* __restrict__ out)
{
    const int b    = blockIdx.x;
    const int w    = threadIdx.x >> 5;
    const int lane = threadIdx.x & 31;

    float cy[32];
#pragma unroll
    for (int q = 0; q < 32; ++q) cy[q] = 0.f;
    float lsesum = 0.f;

    for (int i = 0; i < 16; ++i) {
        int row = b * 128 + w * 16 + i;

        // exact row max / argmax of v: scan 32 slices in ascending column order
        float m = -FLT_MAX;
        int idx = 0;
        const float4* RP = (const float4*)&g_rpart[(size_t)row * 32];
#pragma unroll
        for (int bb = 0; bb < 16; ++bb) {
            float4 pp = __ldg(&RP[bb]);
            if (pp.x > m) { m = pp.x; idx = __float_as_int(pp.y); }
            if (pp.z > m) { m = pp.z; idx = __float_as_int(pp.w); }
        }
        const float mu = m + __ldg(&g_x2[row]);   // max in u-space

        const uint4* L = (const uint4*)(g_logitsh + (size_t)row * K_PROTO);
        uint4 v[4];
#pragma unroll
        for (int j = 0; j < 4; ++j) v[j] = __ldg(&L[j * 32 + lane]);

        float e[32];
        float s = 0.f;
#pragma unroll
        for (int j = 0; j < 4; ++j) {
            const uint32_t* pv = (const uint32_t*)&v[j];
#pragma unroll
            for (int h = 0; h < 4; ++h) {
                float2 f = __half22float2(*(const __half2*)&pv[h]);
                float e0 = __expf(f.x - mu);
                float e1 = __expf(f.y - mu);
                e[j * 8 + h * 2 + 0] = e0;
                e[j * 8 + h * 2 + 1] = e1;
                s += e0 + e1;
            }
        }
#pragma unroll
        for (int off = 16; off; off >>= 1)
            s += __shfl_xor_sync(0xffffffffu, s, off);
        lsesum += m + __logf(s);                  // lse of v
        float inv = 1.f / s;
#pragma unroll
        for (int q = 0; q < 32; ++q) cy[q] += e[q] * inv;

        // quantized[row,:] = P[idx,:]
        const float4* Pr = (const float4*)(P + (size_t)idx * D_DIM);
        float4* Or = (float4*)(out + (size_t)row * D_DIM);
        Or[lane]      = __ldg(&Pr[lane]);
        Or[lane + 32] = __ldg(&Pr[lane + 32]);
    }

    __shared__ float s_y[1024];
    __shared__ float s_lse[8];
    for (int q = threadIdx.x; q < 1024; q += 256) s_y[q] = 0.f;
    __syncthreads();
    for (int w2 = 0; w2 < 8; ++w2) {
        if (w == w2) {
#pragma unroll
            for (int j = 0; j < 4; ++j)
#pragma unroll
                for (int t = 0; t < 8; ++t)
                    s_y[(j * 32 + lane) * 8 + t] += cy[j * 8 + t];
        }
        __syncthreads();
    }
    if (lane == 0) s_lse[w] = lsesum;
    __syncthreads();
    for (int q = threadIdx.x; q < 1024; q += 256)
        g_part_y[b * 1024 + q] = s_y[q];
    if (threadIdx.x == 0) {
        double t = 0.0;
        for (int q = 0; q < 8; ++q) t += (double)s_lse[q];
        g_part_lse[b] = t;
    }
}

// ===========================================================================
// K3: column reduce partials (double, deterministic)
// ===========================================================================
__global__ void colreduce_kernel()
{
    int k = blockIdx.x * 128 + threadIdx.x;
    double sy = 0.0;
    for (int bb = 0; bb < 256; ++bb)
        sy += (double)g_part_y[bb * 1024 + k];
    double sv = 0.0;
    for (int bb = 0; bb < 512; ++bb)
        sv += (double)g_vpart[(size_t)bb * 1024 + k];
    g_coly[k] = sy;
    g_colv[k] = sv;
}

// ===========================================================================
// K4: final scalar
// ===========================================================================
__global__ void final_kernel(float* __restrict__ out, int out_size)
{
    const int t = threadIdx.x;
    double lse_total = 0.0;
    for (int q = 0; q < 256; ++q) lse_total += g_part_lse[q];
    const double lse_mean = lse_total * (1.0 / N_ROWS);

    double t1 = 0.0, t2 = 0.0;
    for (int k = t; k < K_PROTO; k += 256) {
        double prior = g_coly[k] * (1.0 / N_ROWS) + 1e-6;
        double cmlp  = g_colv[k] * (1.0 / N_ROWS) - lse_mean;
        t1 += prior * log(prior);
        t2 += prior * cmlp;
    }
    __shared__ double r1[256];
    __shared__ double r2[256];
    r1[t] = t1; r2[t] = t2;
    __syncthreads();
    for (int off = 128; off; off >>= 1) {
        if (t < off) { r1[t] += r1[t + off]; r2[t] += r2[t + off]; }
        __syncthreads();
    }
    if (t == 0) {
        double capacity = r1[0] - r2[0];
        double ent      = -r1[0];
        out[out_size - 1] = (float)(capacity - 0.001 * ent);
    }
}

// ===========================================================================
extern "C" void kernel_launch(void* const* d_in, const int* in_sizes, int n_in,
                              void* d_out, int out_size)
{
    const float* X = (const float*)d_in[0];   // latents    [32768,256]
    const float* P = (const float*)d_in[1];   // prototypes [1024,256]
    const float* G = (const float*)d_in[2];   // gumbel     [32768,1024]
    float* out = (float*)d_out;

    cudaFuncSetAttribute(gemm_mma_kernel,
                         cudaFuncAttributeMaxDynamicSharedMemorySize, GEMM_SMEM);

    __nv_bfloat16 *xhi, *xlo, *phi, *plo;
    float *x2, *p2;
    cudaGetSymbolAddress((void**)&xhi, g_xhi);
    cudaGetSymbolAddress((void**)&xlo, g_xlo);
    cudaGetSymbolAddress((void**)&phi, g_phi);
    cudaGetSymbolAddress((void**)&plo, g_plo);
    cudaGetSymbolAddress((void**)&x2, g_x2);
    cudaGetSymbolAddress((void**)&p2, g_p2);

    prep_kernel<<<N_ROWS / 8, 256>>>(X, xhi, xlo, x2, N_ROWS);
    prep_kernel<<<K_PROTO / 8, 256>>>(P, phi, plo, p2, K_PROTO);
    gemm_mma_kernel<<<dim3(K_PROTO / NT, N_ROWS / MT), 512, GEMM_SMEM>>>(G);
    softmax_kernel<<<N_ROWS / 128, 256>>>(P, out);
    colreduce_kernel<<<K_PROTO / 128, 128>>>();
    final_kernel<<<1, 256>>>(out, out_size);
}

// round 10
// speedup vs baseline: 1.3703x; 1.3703x over previous
#include <cuda_runtime.h>
#include <cuda_bf16.h>
#include <cuda_fp16.h>
#include <cstdint>
#include <math.h>
#include <float.h>

#define N_ROWS 32768
#define K_PROTO 1024
#define D_DIM 256

// ---- scratch (device globals: no cudaMalloc allowed) ----
__device__ __half         g_logitsh[(size_t)N_ROWS * K_PROTO]; // 64 MB, u = 2dot+g-p2 (approx)
__device__ float          g_x2[N_ROWS];
__device__ float          g_p2[K_PROTO];
__device__ __nv_bfloat16  g_xhi[(size_t)N_ROWS * D_DIM];
__device__ __nv_bfloat16  g_phi[(size_t)K_PROTO * D_DIM];
__device__ float          g_part_y[512 * K_PROTO];             // colsum(y_soft) per softmax block
__device__ float          g_vpart[512 * K_PROTO];              // colsum(v) per (m_block, wm)
__device__ double         g_part_lse[512];                     // sum(lse) per softmax block
__device__ double         g_coly[K_PROTO];
__device__ double         g_colv[K_PROTO];

__device__ __forceinline__ uint32_t smem_u32(const void* p) {
    uint32_t a;
    asm("{ .reg .u64 t; cvta.to.shared.u64 t, %1; cvt.u32.u64 %0, t; }"
        : "=r"(a) : "l"(p));
    return a;
}
__device__ __forceinline__ void cp16(uint32_t saddr, const void* g) {
    asm volatile("cp.async.cg.shared.global [%0], [%1], 16;" :: "r"(saddr), "l"(g) : "memory");
}

// ===========================================================================
// K0: prep — warp per row: bf16 hi + row squared norm.
// ===========================================================================
__global__ void prep_kernel(const float* __restrict__ src,
                            __nv_bfloat16* __restrict__ hi,
                            float* __restrict__ sq, int rows)
{
    int warp = (blockIdx.x * blockDim.x + threadIdx.x) >> 5;
    int lane = threadIdx.x & 31;
    if (warp >= rows) return;
    const float4* s = (const float4*)(src + (size_t)warp * D_DIM);
    uint2* H = (uint2*)(hi + (size_t)warp * D_DIM);
    float acc = 0.f;
#pragma unroll
    for (int i = 0; i < 2; ++i) {
        int c = lane + 32 * i;
        float4 v = __ldg(&s[c]);
        acc += v.x * v.x + v.y * v.y + v.z * v.z + v.w * v.w;
        __nv_bfloat162 a; a.x = __float2bfloat16(v.x); a.y = __float2bfloat16(v.y);
        __nv_bfloat162 b; b.x = __float2bfloat16(v.z); b.y = __float2bfloat16(v.w);
        uint2 hv; hv.x = *(uint32_t*)&a; hv.y = *(uint32_t*)&b;
        H[c] = hv;
    }
#pragma unroll
    for (int off = 16; off; off >>= 1)
        acc += __shfl_xor_sync(0xffffffffu, acc, off);
    if (lane == 0) sq[warp] = acc;
}

// ===========================================================================
// K1: bf16 mma.sync GEMM, single hi*hi term, K=256 in 4 k64 stages.
//     CTA 128x256, 512 threads, warp tile 64x32, all stages prefetched.
//     epilogue: u = 2dot+g-p2 -> fp16 store; colsum(v = u - x2) fp32.
// ===========================================================================
#define MT 128
#define NT 256
#define STAGE_BYTES 49152          // A 16K + B 32K
#define GEMM_SMEM   (4 * STAGE_BYTES)   // 192 KB

__device__ __forceinline__ void issue_stage(int c, uint32_t sbase, int m0, int n0, int tid)
{
    const int koff = c * 64;
    const uint32_t bufA = sbase + (uint32_t)c * STAGE_BYTES;
    const uint32_t bufB = bufA + 16384;
#pragma unroll
    for (int it = 0; it < 2; ++it) {
        int i = tid + 512 * it, row = i >> 3, cc = i & 7;
        cp16(bufA + row * 128 + ((cc ^ (row & 7)) << 4),
             g_xhi + (size_t)(m0 + row) * D_DIM + koff + cc * 8);
    }
#pragma unroll
    for (int it = 0; it < 4; ++it) {
        int i = tid + 512 * it, row = i >> 3, cc = i & 7;
        cp16(bufB + row * 128 + ((cc ^ (row & 7)) << 4),
             g_phi + (size_t)(n0 + row) * D_DIM + koff + cc * 8);
    }
    asm volatile("cp.async.commit_group;" ::: "memory");
}

__global__ void __launch_bounds__(512, 1)
gemm_mma_kernel(const float* __restrict__ G)
{
    extern __shared__ __align__(128) char sm[];
    const uint32_t sbase = smem_u32(sm);
    const int tid  = threadIdx.x;
    const int warp = tid >> 5;
    const int lane = tid & 31;
    const int wm   = warp >> 3;          // 0..1
    const int wn   = warp & 7;           // 0..7
    const int m0   = blockIdx.y * MT;
    const int n0   = blockIdx.x * NT;

    float d[4][4][4];
#pragma unroll
    for (int mi = 0; mi < 4; ++mi)
#pragma unroll
        for (int ni = 0; ni < 4; ++ni)
#pragma unroll
            for (int q = 0; q < 4; ++q) d[mi][ni][q] = 0.f;

    issue_stage(0, sbase, m0, n0, tid);
    issue_stage(1, sbase, m0, n0, tid);
    issue_stage(2, sbase, m0, n0, tid);
    issue_stage(3, sbase, m0, n0, tid);

#pragma unroll
    for (int c = 0; c < 4; ++c) {
        if      (c == 0) asm volatile("cp.async.wait_group 3;" ::: "memory");
        else if (c == 1) asm volatile("cp.async.wait_group 2;" ::: "memory");
        else if (c == 2) asm volatile("cp.async.wait_group 1;" ::: "memory");
        else             asm volatile("cp.async.wait_group 0;" ::: "memory");
        __syncthreads();

        const uint32_t bufA = sbase + (uint32_t)c * STAGE_BYTES;
        const uint32_t bufB = bufA + 16384;
#pragma unroll
        for (int ks = 0; ks < 4; ++ks) {
            uint32_t a[16], br[8];
#pragma unroll
            for (int mi = 0; mi < 4; ++mi) {
                int row = wm * 64 + mi * 16 + (lane & 15);
                int cc  = ks * 2 + (lane >> 4);
                uint32_t ad = bufA + row * 128 + ((cc ^ (row & 7)) << 4);
                asm volatile("ldmatrix.sync.aligned.m8n8.x4.shared.b16 {%0,%1,%2,%3}, [%4];"
                    : "=r"(a[mi*4+0]), "=r"(a[mi*4+1]), "=r"(a[mi*4+2]), "=r"(a[mi*4+3])
                    : "r"(ad));
            }
#pragma unroll
            for (int p = 0; p < 2; ++p) {
                int nrow = wn * 32 + p * 16 + ((lane >> 4) << 3) + (lane & 7);
                int cc   = ks * 2 + ((lane >> 3) & 1);
                uint32_t bd = bufB + nrow * 128 + ((cc ^ (nrow & 7)) << 4);
                asm volatile("ldmatrix.sync.aligned.m8n8.x4.shared.b16 {%0,%1,%2,%3}, [%4];"
                    : "=r"(br[p*4+0]), "=r"(br[p*4+1]), "=r"(br[p*4+2]), "=r"(br[p*4+3])
                    : "r"(bd));
            }
#pragma unroll
            for (int mi = 0; mi < 4; ++mi)
#pragma unroll
                for (int ni = 0; ni < 4; ++ni) {
                    asm volatile(
                        "mma.sync.aligned.m16n8k16.row.col.f32.bf16.bf16.f32 "
                        "{%0,%1,%2,%3}, {%4,%5,%6,%7}, {%8,%9}, {%0,%1,%2,%3};"
                        : "+f"(d[mi][ni][0]), "+f"(d[mi][ni][1]),
                          "+f"(d[mi][ni][2]), "+f"(d[mi][ni][3])
                        : "r"(a[mi*4+0]), "r"(a[mi*4+1]), "r"(a[mi*4+2]), "r"(a[mi*4+3]),
                          "r"(br[ni*2+0]), "r"(br[ni*2+1]));
                }
        }
    }

    // ---- epilogue: u = 2dot+g-p2 (fp16 store); colsum of v = u - x2 ----
    float cs[8];
#pragma unroll
    for (int j = 0; j < 8; ++j) cs[j] = 0.f;

#pragma unroll
    for (int mi = 0; mi < 4; ++mi) {
        int r0 = m0 + wm * 64 + mi * 16 + (lane >> 2);
        float x20 = g_x2[r0], x21 = g_x2[r0 + 8];
#pragma unroll
        for (int ni = 0; ni < 4; ++ni) {
            int col = n0 + wn * 32 + ni * 8 + (lane & 3) * 2;
            float2 p2v = *(const float2*)&g_p2[col];
            float2 ga = __ldg((const float2*)(G + (size_t)r0 * K_PROTO + col));
            float2 gb = __ldg((const float2*)(G + (size_t)(r0 + 8) * K_PROTO + col));
            float2 u0, u1;
            u0.x = fmaf(2.f, d[mi][ni][0], ga.x) - p2v.x;
            u0.y = fmaf(2.f, d[mi][ni][1], ga.y) - p2v.y;
            u1.x = fmaf(2.f, d[mi][ni][2], gb.x) - p2v.x;
            u1.y = fmaf(2.f, d[mi][ni][3], gb.y) - p2v.y;
            __half2 h0 = __floats2half2_rn(u0.x, u0.y);
            __half2 h1 = __floats2half2_rn(u1.x, u1.y);
            *(uint32_t*)(g_logitsh + (size_t)r0 * K_PROTO + col)       = *(uint32_t*)&h0;
            *(uint32_t*)(g_logitsh + (size_t)(r0 + 8) * K_PROTO + col) = *(uint32_t*)&h1;
            cs[ni * 2 + 0] += (u0.x - x20) + (u1.x - x21);
            cs[ni * 2 + 1] += (u0.y - x20) + (u1.y - x21);
        }
    }
    // colsum(v): reduce over the 8 lanes sharing each column (xor 4,8,16)
#pragma unroll
    for (int j = 0; j < 8; ++j) {
#pragma unroll
        for (int off = 4; off <= 16; off <<= 1)
            cs[j] += __shfl_xor_sync(0xffffffffu, cs[j], off);
    }
    if (lane < 4) {
        float* dst = g_vpart + (size_t)(blockIdx.y * 2 + wm) * K_PROTO;
#pragma unroll
        for (int j = 0; j < 8; ++j) {
            int col = n0 + wn * 32 + (j >> 1) * 8 + lane * 2 + (j & 1);
            dst[col] = cs[j];
        }
    }
}

// ===========================================================================
// K2: softmax from fp16 approx logits + EXACT argmax via candidate fixup.
//     512 blocks x 256 threads; warp handles 8 rows; lane owns 32 columns
//     k = (j*32+lane)*8 + t, j=0..3, t=0..7.
// ===========================================================================
#define FIX_MARGIN 0.03f

__global__ void __launch_bounds__(256)
softmax_kernel(const float* __restrict__ X, const float* __restrict__ P,
               const float* __restrict__ G, float* __restrict__ out)
{
    const int b    = blockIdx.x;
    const int w    = threadIdx.x >> 5;
    const int lane = threadIdx.x & 31;

    float cy[32];
#pragma unroll
    for (int q = 0; q < 32; ++q) cy[q] = 0.f;
    float lsesum = 0.f;

    for (int i = 0; i < 8; ++i) {
        int row = b * 64 + w * 8 + i;
        const float x2r = __ldg(&g_x2[row]);

        const uint4* L = (const uint4*)(g_logitsh + (size_t)row * K_PROTO);
        uint4 raw[4];
#pragma unroll
        for (int j = 0; j < 4; ++j) raw[j] = __ldg(&L[j * 32 + lane]);

        float f[32];
#pragma unroll
        for (int j = 0; j < 4; ++j) {
            const uint32_t* pv = (const uint32_t*)&raw[j];
#pragma unroll
            for (int h = 0; h < 4; ++h) {
                float2 fv = __half22float2(*(const __half2*)&pv[h]);
                f[j * 8 + h * 2 + 0] = fv.x;
                f[j * 8 + h * 2 + 1] = fv.y;
            }
        }

        // fp16-level max (for exp shift + candidate threshold)
        float m = -FLT_MAX;
#pragma unroll
        for (int q = 0; q < 32; ++q) m = fmaxf(m, f[q]);
#pragma unroll
        for (int off = 16; off; off >>= 1)
            m = fmaxf(m, __shfl_xor_sync(0xffffffffu, m, off));

        // candidate mask: values within margin of fp16 max
        const float thr = m - FIX_MARGIN;
        uint32_t cmask = 0;
#pragma unroll
        for (int q = 0; q < 32; ++q)
            if (f[q] >= thr) cmask |= (1u << q);

        // exact argmax over candidates (warp-cooperative fp32 recompute)
        float vbest = -FLT_MAX;
        int kbest = 0;
        const float4* Xr = (const float4*)(X + (size_t)row * D_DIM);
        float4 xa = __ldg(&Xr[lane * 2]);
        float4 xb = __ldg(&Xr[lane * 2 + 1]);
        for (;;) {
            uint32_t myk = 0xFFFFFFFFu;
            if (cmask) {
                int bpos = __ffs(cmask) - 1;
                myk = ((uint32_t)(bpos >> 3) << 8) | ((uint32_t)lane << 3) | (uint32_t)(bpos & 7);
            }
            uint32_t kstar = __reduce_min_sync(0xffffffffu, myk);
            if (kstar == 0xFFFFFFFFu) break;
            const float4* Pr = (const float4*)(P + (size_t)kstar * D_DIM);
            float4 pa = __ldg(&Pr[lane * 2]);
            float4 pb = __ldg(&Pr[lane * 2 + 1]);
            float dot = xa.x * pa.x;
            dot = fmaf(xa.y, pa.y, dot);
            dot = fmaf(xa.z, pa.z, dot);
            dot = fmaf(xa.w, pa.w, dot);
            dot = fmaf(xb.x, pb.x, dot);
            dot = fmaf(xb.y, pb.y, dot);
            dot = fmaf(xb.z, pb.z, dot);
            dot = fmaf(xb.w, pb.w, dot);
#pragma unroll
            for (int off = 16; off; off >>= 1)
                dot += __shfl_xor_sync(0xffffffffu, dot, off);
            float vex = fmaf(2.f, dot, __ldg(&G[(size_t)row * K_PROTO + kstar]))
                        - x2r - __ldg(&g_p2[kstar]);
            if (vex > vbest || (vex == vbest && (int)kstar < kbest)) {
                vbest = vex; kbest = (int)kstar;
            }
            if (myk == kstar) cmask &= cmask - 1;
        }

        // exp / sums (in u-space, shift by fp16 max m)
        float s = 0.f;
#pragma unroll
        for (int q = 0; q < 32; ++q) { f[q] = __expf(f[q] - m); s += f[q]; }
#pragma unroll
        for (int off = 16; off; off >>= 1)
            s += __shfl_xor_sync(0xffffffffu, s, off);
        lsesum += (m - x2r) + __logf(s);
        float inv = 1.f / s;
#pragma unroll
        for (int q = 0; q < 32; ++q) cy[q] += f[q] * inv;

        // quantized[row,:] = P[kbest,:]
        const float4* Pq = (const float4*)(P + (size_t)kbest * D_DIM);
        float4* Or = (float4*)(out + (size_t)row * D_DIM);
        Or[lane]      = __ldg(&Pq[lane]);
        Or[lane + 32] = __ldg(&Pq[lane + 32]);
    }

    // deterministic cross-warp reduction
    __shared__ float s_y[1024];
    __shared__ float s_lse[8];
    for (int q = threadIdx.x; q < 1024; q += 256) s_y[q] = 0.f;
    __syncthreads();
    for (int w2 = 0; w2 < 8; ++w2) {
        if (w == w2) {
#pragma unroll
            for (int j = 0; j < 4; ++j)
#pragma unroll
                for (int t = 0; t < 8; ++t)
                    s_y[(j * 32 + lane) * 8 + t] += cy[j * 8 + t];
        }
        __syncthreads();
    }
    if (lane == 0) s_lse[w] = lsesum;
    __syncthreads();
    for (int q = threadIdx.x; q < 1024; q += 256)
        g_part_y[b * 1024 + q] = s_y[q];
    if (threadIdx.x == 0) {
        double t = 0.0;
        for (int q = 0; q < 8; ++q) t += (double)s_lse[q];
        g_part_lse[b] = t;
    }
}

// ===========================================================================
// K3: column reduce partials (double, deterministic)
// ===========================================================================
__global__ void colreduce_kernel()
{
    int k = blockIdx.x * 128 + threadIdx.x;
    double sy = 0.0;
    for (int bb = 0; bb < 512; ++bb)
        sy += (double)g_part_y[(size_t)bb * 1024 + k];
    double sv = 0.0;
    for (int bb = 0; bb < 512; ++bb)
        sv += (double)g_vpart[(size_t)bb * 1024 + k];
    g_coly[k] = sy;
    g_colv[k] = sv;
}

// ===========================================================================
// K4: final scalar
// ===========================================================================
__global__ void final_kernel(float* __restrict__ out, int out_size)
{
    const int t = threadIdx.x;
    double lse_total = 0.0;
    for (int q = 0; q < 512; ++q) lse_total += g_part_lse[q];
    const double lse_mean = lse_total * (1.0 / N_ROWS);

    double t1 = 0.0, t2 = 0.0;
    for (int k = t; k < K_PROTO; k += 256) {
        double prior = g_coly[k] * (1.0 / N_ROWS) + 1e-6;
        double cmlp  = g_colv[k] * (1.0 / N_ROWS) - lse_mean;
        t1 += prior * log(prior);
        t2 += prior * cmlp;
    }
    __shared__ double r1[256];
    __shared__ double r2[256];
    r1[t] = t1; r2[t] = t2;
    __syncthreads();
    for (int off = 128; off; off >>= 1) {
        if (t < off) { r1[t] += r1[t + off]; r2[t] += r2[t + off]; }
        __syncthreads();
    }
    if (t == 0) {
        double capacity = r1[0] - r2[0];
        double ent      = -r1[0];
        out[out_size - 1] = (float)(capacity - 0.001 * ent);
    }
}

// ===========================================================================
extern "C" void kernel_launch(void* const* d_in, const int* in_sizes, int n_in,
                              void* d_out, int out_size)
{
    const float* X = (const float*)d_in[0];   // latents    [32768,256]
    const float* P = (const float*)d_in[1];   // prototypes [1024,256]
    const float* G = (const float*)d_in[2];   // gumbel     [32768,1024]
    float* out = (float*)d_out;

    cudaFuncSetAttribute(gemm_mma_kernel,
                         cudaFuncAttributeMaxDynamicSharedMemorySize, GEMM_SMEM);

    __nv_bfloat16 *xhi, *phi;
    float *x2, *p2;
    cudaGetSymbolAddress((void**)&xhi, g_xhi);
    cudaGetSymbolAddress((void**)&phi, g_phi);
    cudaGetSymbolAddress((void**)&x2, g_x2);
    cudaGetSymbolAddress((void**)&p2, g_p2);

    prep_kernel<<<N_ROWS / 8, 256>>>(X, xhi, x2, N_ROWS);
    prep_kernel<<<K_PROTO / 8, 256>>>(P, phi, p2, K_PROTO);
    gemm_mma_kernel<<<dim3(K_PROTO / NT, N_ROWS / MT), 512, GEMM_SMEM>>>(G);
    softmax_kernel<<<N_ROWS / 64, 256>>>(X, P, G, out);
    colreduce_kernel<<<K_PROTO / 128, 128>>>();
    final_kernel<<<1, 256>>>(out, out_size);
}